// round 14
// baseline (speedup 1.0000x reference)
#include <cuda_runtime.h>
#include <cuda_fp16.h>
#include <math.h>
#include <stdint.h>

// Problem constants
#define BB   4
#define TT   4096
#define NN   1024
#define BT   16384
#define NRAW 4096
#define NCHUNK 32
#define LCHUNK 128

// fp16 GEMM tiling (GEMM2 + sigma chain)
#define GBN 128
#define GBK 64
#define KDIM 1024
#define KCH  16

#define NSQ 7
#define NMV 5

#define SM128 147456                     // 3 * (16384 + 32768)  (fp16 TBM=128)
#define SM64  122880                     // 3 * ( 8192 + 32768)  (fp16 TBM=64)
// int8 GEMM1: stage = A(64*128 hi+lo = 16K) + B(128*128 hi+lo = 32K) = 48K, 3 stages
#define SMS8  147456

// ---------------------------------------------------------------------------
// Device scratch
// ---------------------------------------------------------------------------
__device__ __align__(128) float g_RAW[(size_t)BT * NRAW];
__device__ __align__(128) int8_t g_As8h[(size_t)BT * KDIM];
__device__ __align__(128) int8_t g_As8l[(size_t)BT * KDIM];
__device__ __align__(128) int8_t g_Bs8h[(size_t)NRAW * KDIM];
__device__ __align__(128) int8_t g_Bs8l[(size_t)NRAW * KDIM];
__device__ float g_sa[BT];
__device__ float g_sb[NRAW];
__device__ __align__(128) __half g_Whi[(size_t)NN * KDIM];            // W_out (GEMM2)
__device__ __align__(128) __half g_Wlo[(size_t)NN * KDIM];
__device__ __align__(128) __half g_Yhi[(size_t)BT * NN];
__device__ float g_AggA[BB * NCHUNK * NN];
__device__ float g_AggB[BB * NCHUNK * NN];
__device__ int   g_flag[BB * NCHUNK * 8];

// spectral-norm machinery
__device__ __align__(128) __half g_Shi[2 * 1024 * 1024];
__device__ __align__(128) __half g_Slo[2 * 1024 * 1024];
__device__ __align__(128) float g_Gk[2 * 1024 * 1024];
__device__ __align__(128) float g_G0[2 * 1024 * 1024];
__device__ float g_pv[2 * 1024];
__device__ float g_pw[2 * 1024];
__device__ float g_trace[32];
__device__ float g_acc[2];
__device__ float g_sigma[2];

// ---------------------------------------------------------------------------
// PTX helpers
// ---------------------------------------------------------------------------
__device__ __forceinline__ uint32_t smem_u32(const void* p) {
    uint32_t a;
    asm("{ .reg .u64 t; cvta.to.shared.u64 t, %1; cvt.u32.u64 %0, t; }" : "=r"(a) : "l"(p));
    return a;
}

#define CP_ASYNC16(dst, src) \
    asm volatile("cp.async.cg.shared.global [%0], [%1], 16;" :: "r"(dst), "l"(src))
#define CP_COMMIT() asm volatile("cp.async.commit_group;" ::: "memory")
#define CP_WAIT1()  asm volatile("cp.async.wait_group 1;" ::: "memory")
#define CP_WAIT0()  asm volatile("cp.async.wait_group 0;" ::: "memory")

#define LDMATRIX_X4(r0, r1, r2, r3, addr) \
    asm volatile("ldmatrix.sync.aligned.m8n8.x4.shared.b16 {%0,%1,%2,%3}, [%4];" \
                 : "=r"(r0), "=r"(r1), "=r"(r2), "=r"(r3) : "r"(addr))

#define MMA_FP16(d, a, b) \
    asm volatile("mma.sync.aligned.m16n8k16.row.col.f32.f16.f16.f32 " \
        "{%0,%1,%2,%3}, {%4,%5,%6,%7}, {%8,%9}, {%0,%1,%2,%3};" \
        : "+f"((d)[0]), "+f"((d)[1]), "+f"((d)[2]), "+f"((d)[3]) \
        : "r"((a)[0]), "r"((a)[1]), "r"((a)[2]), "r"((a)[3]), "r"((b)[0]), "r"((b)[1]))

#define MMA_S8(d, a, b) \
    asm volatile("mma.sync.aligned.m16n8k32.row.col.s32.s8.s8.s32 " \
        "{%0,%1,%2,%3}, {%4,%5,%6,%7}, {%8,%9}, {%0,%1,%2,%3};" \
        : "+r"((d)[0]), "+r"((d)[1]), "+r"((d)[2]), "+r"((d)[3]) \
        : "r"((a)[0]), "r"((a)[1]), "r"((a)[2]), "r"((a)[3]), "r"((b)[0]), "r"((b)[1]))

// ---------------------------------------------------------------------------
// fp16 split helpers
// ---------------------------------------------------------------------------
__device__ __forceinline__ void split4h(const float4 v, uint2& H, uint2& L) {
    union { __half b[4]; uint2 u; } h, l;
    float x[4] = {v.x, v.y, v.z, v.w};
    #pragma unroll
    for (int j = 0; j < 4; j++) {
        __half hb = __float2half_rn(x[j]);
        h.b[j] = hb;
        l.b[j] = __float2half_rn(x[j] - __half2float(hb));
    }
    H = h.u; L = l.u;
}
__device__ __forceinline__ uint2 hi4h(const float4 v) {
    union { __half b[4]; uint2 u; } h;
    h.b[0] = __float2half_rn(v.x); h.b[1] = __float2half_rn(v.y);
    h.b[2] = __float2half_rn(v.z); h.b[3] = __float2half_rn(v.w);
    return h.u;
}

// Per-row int8 2-term quantization helper: block = one 1024-float row.
// Each of 256 threads owns one float4. Returns after writing hi/lo uchar4 + scale.
__device__ __forceinline__ void quant_row(const float4 v, int row, int i4,
                                          int8_t* __restrict__ hi8, int8_t* __restrict__ lo8,
                                          float* __restrict__ srow, float* red) {
    int tid = threadIdx.x, lane = tid & 31, w = tid >> 5;
    float m = fmaxf(fmaxf(fabsf(v.x), fabsf(v.y)), fmaxf(fabsf(v.z), fabsf(v.w)));
    #pragma unroll
    for (int o = 16; o > 0; o >>= 1) m = fmaxf(m, __shfl_xor_sync(0xffffffffu, m, o));
    if (lane == 0) red[w] = m;
    __syncthreads();
    if (w == 0) {
        float q = (lane < 8) ? red[lane] : 0.f;
        #pragma unroll
        for (int o = 4; o > 0; o >>= 1) q = fmaxf(q, __shfl_xor_sync(0xffffffffu, q, o));
        if (lane == 0) red[0] = fmaxf(q, 1e-20f);
    }
    __syncthreads();
    float rowmax = red[0];
    float s = rowmax / 16256.0f;
    float inv = 16256.0f / rowmax;
    float x[4] = {v.x, v.y, v.z, v.w};
    union { int8_t b[4]; uint32_t u; } H, L;
    #pragma unroll
    for (int j = 0; j < 4; j++) {
        float q = x[j] * inv;                       // in [-16256, 16256]
        float hq = rintf(q * (1.0f / 128.0f));      // [-127, 127]
        float lq = rintf(q - 128.0f * hq);          // [-64, 64]
        H.b[j] = (int8_t)(int)hq;
        L.b[j] = (int8_t)(int)lq;
    }
    ((uint32_t*)hi8)[(size_t)row * 256 + i4] = H.u;
    ((uint32_t*)lo8)[(size_t)row * 256 + i4] = L.u;
    if (tid == 0) srow[row] = s;
}

// All input prep in ONE launch (block-range dispatch) + scan-flag clear.
__global__ void __launch_bounds__(256) split_all(
    const float* __restrict__ u, const float* __restrict__ Wp,
    const float* __restrict__ Win, const float* __restrict__ Wout)
{
    __shared__ float red[8];
    int blk = blockIdx.x, tid = threadIdx.x;
    if (blk < 16384) {
        // u -> int8 2-term, one row per block
        float4 v = ((const float4*)u)[blk * 256 + tid];
        quant_row(v, blk, tid, g_As8h, g_As8l, g_sa, red);
    } else if (blk < 19456) {
        // Wp rows 0..3071 -> B int8
        int row = blk - 16384;
        float4 v = ((const float4*)Wp)[row * 256 + tid];
        quant_row(v, row, tid, g_Bs8h, g_Bs8l, g_sb, red);
    } else if (blk < 20480) {
        // W_in -> B rows 3072..4095 int8
        int row = blk - 19456;
        float4 v = ((const float4*)Win)[row * 256 + tid];
        quant_row(v, 3072 + row, tid, g_Bs8h, g_Bs8l, g_sb, red);
    } else if (blk < 21504) {
        int i = (blk - 20480) * 256 + tid;
        uint2 H, L; split4h(((const float4*)Wout)[i], H, L);
        ((uint2*)g_Whi)[i] = H; ((uint2*)g_Wlo)[i] = L;
    } else if (blk < 22528) {
        int i = (blk - 21504) * 256 + tid;
        uint2 H, L; split4h(((const float4*)Win)[i], H, L);
        ((uint2*)g_Shi)[i] = H; ((uint2*)g_Slo)[i] = L;
    } else if (blk < 23552) {
        int i = (blk - 22528) * 256 + tid;
        uint2 H, L; split4h(((const float4*)Wout)[i], H, L);
        ((uint2*)g_Shi)[262144 + i] = H; ((uint2*)g_Slo)[262144 + i] = L;
    } else {
        int i = (blk - 23552) * 256 + tid;       // 4 blocks: clear 1024 lookback flags
        g_flag[i] = 0;
    }
}

// g_Gk[g] * (1024/trace[g][step]) -> g_Shi[g]  (hi only for squarings k>=1)
__global__ void __launch_bounds__(256) split_scaled(int step) {
    int g = blockIdx.y;
    int i = blockIdx.x * 256 + threadIdx.x;
    float s = 1024.0f / g_trace[g * 16 + step];
    float4 v = ((const float4*)(g_Gk + (size_t)g * 1048576))[i];
    v.x *= s; v.y *= s; v.z *= s; v.w *= s;
    ((uint2*)(g_Shi + (size_t)g * 1048576))[i] = hi4h(v);
}

__global__ void __launch_bounds__(1024) init_spec() {
    int t = threadIdx.x;
    float v = 0.5f + __sinf((float)t * 0.7311f);
    g_pv[t] = v;
    g_pv[1024 + t] = v;
    if (t < 32) g_trace[t] = 0.f;
    if (t < 2) g_acc[t] = 0.f;
}

// ---------------------------------------------------------------------------
// Small matvec helpers (batched over g)
// ---------------------------------------------------------------------------
__global__ void __launch_bounds__(256) mv_kernel() {
    int g = blockIdx.y;
    const float* G = g_Gk + (size_t)g * 1048576;
    const float4* V4 = (const float4*)(g_pv + g * 1024);
    int w = threadIdx.x >> 5, lane = threadIdx.x & 31;
    #pragma unroll
    for (int rr = 0; rr < 2; rr++) {
        int r = blockIdx.x * 16 + w * 2 + rr;
        const float4* Gr = (const float4*)(G + (size_t)r * 1024);
        float s = 0.f;
        #pragma unroll 4
        for (int j = lane; j < 256; j += 32) {
            float4 a = Gr[j], x = V4[j];
            s += a.x * x.x + a.y * x.y + a.z * x.z + a.w * x.w;
        }
        #pragma unroll
        for (int o = 16; o > 0; o >>= 1) s += __shfl_xor_sync(0xffffffffu, s, o);
        if (lane == 0) g_pw[g * 1024 + r] = s;
    }
}

__global__ void __launch_bounds__(1024) vnorm_kernel() {
    __shared__ float sp[32];
    int g = blockIdx.x;
    int t = threadIdx.x, lane = t & 31, w = t >> 5;
    float v = g_pw[g * 1024 + t];
    float p = v * v;
    #pragma unroll
    for (int o = 16; o > 0; o >>= 1) p += __shfl_xor_sync(0xffffffffu, p, o);
    if (lane == 0) sp[w] = p;
    __syncthreads();
    if (w == 0) {
        float q = sp[lane];
        #pragma unroll
        for (int o = 16; o > 0; o >>= 1) q += __shfl_xor_sync(0xffffffffu, q, o);
        if (lane == 0) sp[0] = rsqrtf(q);
    }
    __syncthreads();
    g_pv[g * 1024 + t] = v * sp[0];
}

__global__ void __launch_bounds__(256) rq_kernel() {
    int g = blockIdx.y;
    const float* G0 = g_G0 + (size_t)g * 1048576;
    const float4* V4 = (const float4*)(g_pv + g * 1024);
    int w = threadIdx.x >> 5, lane = threadIdx.x & 31;
    float part = 0.f;
    #pragma unroll
    for (int rr = 0; rr < 2; rr++) {
        int r = blockIdx.x * 16 + w * 2 + rr;
        const float4* Gr = (const float4*)(G0 + (size_t)r * 1024);
        float s = 0.f;
        #pragma unroll 4
        for (int j = lane; j < 256; j += 32) {
            float4 a = Gr[j], x = V4[j];
            s += a.x * x.x + a.y * x.y + a.z * x.z + a.w * x.w;
        }
        #pragma unroll
        for (int o = 16; o > 0; o >>= 1) s += __shfl_xor_sync(0xffffffffu, s, o);
        if (lane == 0) part += s * g_pv[g * 1024 + r];
    }
    if (lane == 0) atomicAdd(&g_acc[g], part);
}

__global__ void fin_sigma() {
    if (threadIdx.x < 2)
        g_sigma[threadIdx.x] = fmaxf(1.0f, sqrtf(fmaxf(g_acc[threadIdx.x], 0.f)));
}

// ---------------------------------------------------------------------------
// fp16 HMMA GEMM (MODE 1: GEMM2; MODE 2: sigma squarings)
// TBM x 128 x 64 tiles, 16 warps (4m x 4n), 512 thr, 3-stage pipeline.
// ---------------------------------------------------------------------------
template <int TBM>
__device__ __forceinline__ void load_tiles(
    uint32_t base,
    const __half* __restrict__ Ah,
    const __half* __restrict__ Bh, const __half* __restrict__ Bl,
    int tid, bool two)
{
    constexpr uint32_t AB = TBM * 128;
    uint32_t sA = base, sBhi = base + AB, sBlo = base + AB + 16384;
    #pragma unroll
    for (int it = 0; it < TBM / 64; it++) {
        int idx = tid + it * 512;
        int r = idx >> 3, c8 = idx & 7;
        uint32_t sw = (uint32_t)r * 128 + (((uint32_t)c8 * 16) ^ (((uint32_t)r & 7) << 4));
        CP_ASYNC16(sA + sw, (const char*)(Ah + (size_t)r * KDIM) + c8 * 16);
    }
    #pragma unroll
    for (int it = 0; it < 2; it++) {
        int idx = tid + it * 512;
        int r = idx >> 3, c8 = idx & 7;
        uint32_t sw = (uint32_t)r * 128 + (((uint32_t)c8 * 16) ^ (((uint32_t)r & 7) << 4));
        CP_ASYNC16(sBhi + sw, (const char*)(Bh + (size_t)r * KDIM) + c8 * 16);
        if (two) CP_ASYNC16(sBlo + sw, (const char*)(Bl + (size_t)r * KDIM) + c8 * 16);
    }
}

template <int MODE, int TBM>
__global__ void __launch_bounds__(512, 1) mma_gemm(float* __restrict__ Cout, int step)
{
    constexpr int MT = TBM / 64;
    constexpr uint32_t AB = TBM * 128;
    constexpr uint32_t STAGE = AB + 32768;
    extern __shared__ char smem[];
    uint32_t sb = smem_u32(smem);
    int tid = threadIdx.x, wid = tid >> 5, lane = tid & 31;
    int m0 = blockIdx.y * TBM;
    int n0 = blockIdx.x * GBN;
    int wm = wid >> 2, wn = wid & 3;
    int m_off = wm * (TBM / 4), n_off = wn * 32;

    const bool two = (MODE != 2) || (step == 0);
    size_t goff = (MODE == 2) ? (size_t)blockIdx.z * 1048576 : 0;
    const __half* Ah = (MODE == 1 ? g_Yhi : g_Shi) + goff + (size_t)m0 * KDIM;
    const __half* Bh = (MODE == 1 ? g_Whi : g_Shi) + goff + (size_t)n0 * KDIM;
    const __half* Bl = (MODE == 1 ? g_Wlo : g_Slo) + goff + (size_t)n0 * KDIM;
    float* C = (MODE == 1) ? Cout : (g_Gk + goff);
    const int ldc = NN;

    float acc[MT][4][4];
    #pragma unroll
    for (int mt = 0; mt < MT; mt++)
        #pragma unroll
        for (int n = 0; n < 4; n++)
            #pragma unroll
            for (int j = 0; j < 4; j++) acc[mt][n][j] = 0.f;

    int lrow = lane & 15;
    uint32_t lcol = ((uint32_t)(lane >> 4)) << 4;

    load_tiles<TBM>(sb,         Ah,      Bh,      Bl,      tid, two); CP_COMMIT();
    load_tiles<TBM>(sb + STAGE, Ah + 64, Bh + 64, Bl + 64, tid, two); CP_COMMIT();

    for (int ch = 0; ch < KCH; ch++) {
        if (ch == KCH - 1) { CP_WAIT0(); } else { CP_WAIT1(); }
        __syncthreads();
        if (ch + 2 < KCH) {
            int k0 = (ch + 2) * GBK;
            load_tiles<TBM>(sb + ((ch + 2) % 3) * STAGE, Ah + k0, Bh + k0, Bl + k0, tid, two);
            CP_COMMIT();
        }
        uint32_t base = sb + (ch % 3) * STAGE;
        #pragma unroll
        for (int ks = 0; ks < 4; ks++) {
            uint32_t cb = (uint32_t)ks * 32 + lcol;
            uint32_t ahi[MT][4];
            #pragma unroll
            for (int mt = 0; mt < MT; mt++) {
                int row = m_off + mt * 16 + lrow;
                uint32_t ad = base + (uint32_t)row * 128 + (cb ^ (((uint32_t)row & 7) << 4));
                LDMATRIX_X4(ahi[mt][0], ahi[mt][1], ahi[mt][2], ahi[mt][3], ad);
            }
            uint32_t bhi[4][2], blo[4][2];
            #pragma unroll
            for (int nt = 0; nt < 2; nt++) {
                int row = n_off + nt * 16 + lrow;
                uint32_t bd = base + AB + (uint32_t)row * 128 + (cb ^ (((uint32_t)row & 7) << 4));
                uint32_t r0, r1, r2, r3;
                LDMATRIX_X4(r0, r1, r2, r3, bd);
                bhi[nt * 2][0] = r0; bhi[nt * 2][1] = r2;
                bhi[nt * 2 + 1][0] = r1; bhi[nt * 2 + 1][1] = r3;
                if (two) {
                    LDMATRIX_X4(r0, r1, r2, r3, bd + 16384);
                    blo[nt * 2][0] = r0; blo[nt * 2][1] = r2;
                    blo[nt * 2 + 1][0] = r1; blo[nt * 2 + 1][1] = r3;
                }
            }
            #pragma unroll
            for (int mt = 0; mt < MT; mt++)
                #pragma unroll
                for (int n = 0; n < 4; n++) {
                    MMA_FP16(acc[mt][n], ahi[mt], bhi[n]);
                    if (two) MMA_FP16(acc[mt][n], ahi[mt], blo[n]);
                }
        }
    }

    float scale = 1.0f;
    if (MODE == 1) scale = 1.0f / (g_sigma[0] * g_sigma[1]);
    int gid = lane >> 2, tig = lane & 3;
    float tp = 0.f;
    bool diag = (MODE == 2) && (m0 < n0 + GBN) && (n0 < m0 + TBM);

    #pragma unroll
    for (int mt = 0; mt < MT; mt++) {
        #pragma unroll
        for (int n = 0; n < 4; n++) {
            int col = n0 + n_off + n * 8 + tig * 2;
            int r0 = m0 + m_off + mt * 16 + gid;
            float2 v0 = make_float2(acc[mt][n][0], acc[mt][n][1]);
            float2 v1 = make_float2(acc[mt][n][2], acc[mt][n][3]);
            if (MODE == 1) {
                v0.x *= scale; v0.y *= scale; v1.x *= scale; v1.y *= scale;
            } else if (diag) {
                if (r0 == col)         tp += v0.x;
                if (r0 == col + 1)     tp += v0.y;
                if (r0 + 8 == col)     tp += v1.x;
                if (r0 + 8 == col + 1) tp += v1.y;
            }
            *(float2*)(C + (size_t)r0 * ldc + col) = v0;
            *(float2*)(C + (size_t)(r0 + 8) * ldc + col) = v1;
            if (MODE == 2 && step == 0) {
                float* C0 = g_G0 + goff;
                *(float2*)(C0 + (size_t)r0 * ldc + col) = v0;
                *(float2*)(C0 + (size_t)(r0 + 8) * ldc + col) = v1;
            }
        }
    }
    if (MODE == 2 && diag && tp != 0.f)
        atomicAdd(&g_trace[blockIdx.z * 16 + step], tp);
}

// ---------------------------------------------------------------------------
// GEMM1: int8 2-term IMMA.  C = sa*sb*(16384*hihi + 128*(hi*lo + lo*hi)) + bias
// 64 x 128 x K tiles, k-chunk = 128 s8 (128 B rows), 16 warps 4x4, warp 16x32.
// s8-k32 fragments are byte-isomorphic to b16-k16 -> identical ldmatrix code.
// ---------------------------------------------------------------------------
#define S8KCH 8
__device__ __forceinline__ void load_tiles_s8(
    uint32_t base,
    const int8_t* __restrict__ Ah, const int8_t* __restrict__ Al,
    const int8_t* __restrict__ Bh, const int8_t* __restrict__ Bl,
    int tid)
{
    uint32_t sAh = base, sAl = base + 8192, sBh = base + 16384, sBl = base + 32768;
    {   // A: 64 rows x 8 x 16B = 512 txns
        int r = tid >> 3, c8 = tid & 7;
        uint32_t sw = (uint32_t)r * 128 + (((uint32_t)c8 * 16) ^ (((uint32_t)r & 7) << 4));
        CP_ASYNC16(sAh + sw, Ah + (size_t)r * KDIM + c8 * 16);
        CP_ASYNC16(sAl + sw, Al + (size_t)r * KDIM + c8 * 16);
    }
    #pragma unroll
    for (int it = 0; it < 2; it++) {     // B: 128 rows x 8 x 16B = 1024 txns
        int idx = tid + it * 512;
        int r = idx >> 3, c8 = idx & 7;
        uint32_t sw = (uint32_t)r * 128 + (((uint32_t)c8 * 16) ^ (((uint32_t)r & 7) << 4));
        CP_ASYNC16(sBh + sw, Bh + (size_t)r * KDIM + c8 * 16);
        CP_ASYNC16(sBl + sw, Bl + (size_t)r * KDIM + c8 * 16);
    }
}

__global__ void __launch_bounds__(512, 1) gemm1_s8(const float* __restrict__ bias)
{
    constexpr uint32_t STAGE = 49152;
    extern __shared__ char smem[];
    uint32_t sb = smem_u32(smem);
    int tid = threadIdx.x, wid = tid >> 5, lane = tid & 31;
    int m0 = blockIdx.y * 64;
    int n0 = blockIdx.x * GBN;
    int wm = wid >> 2, wn = wid & 3;
    int m_off = wm * 16, n_off = wn * 32;

    const int8_t* Ah = g_As8h + (size_t)m0 * KDIM;
    const int8_t* Al = g_As8l + (size_t)m0 * KDIM;
    const int8_t* Bh = g_Bs8h + (size_t)n0 * KDIM;
    const int8_t* Bl = g_Bs8l + (size_t)n0 * KDIM;

    int32_t acc1[4][4], acc2[4][4];
    #pragma unroll
    for (int n = 0; n < 4; n++)
        #pragma unroll
        for (int j = 0; j < 4; j++) { acc1[n][j] = 0; acc2[n][j] = 0; }

    int lrow = lane & 15;
    uint32_t lcol = ((uint32_t)(lane >> 4)) << 4;

    load_tiles_s8(sb,         Ah,       Al,       Bh,       Bl,       tid); CP_COMMIT();
    load_tiles_s8(sb + STAGE, Ah + 128, Al + 128, Bh + 128, Bl + 128, tid); CP_COMMIT();

    for (int ch = 0; ch < S8KCH; ch++) {
        if (ch == S8KCH - 1) { CP_WAIT0(); } else { CP_WAIT1(); }
        __syncthreads();
        if (ch + 2 < S8KCH) {
            int k0 = (ch + 2) * 128;
            load_tiles_s8(sb + ((ch + 2) % 3) * STAGE, Ah + k0, Al + k0, Bh + k0, Bl + k0, tid);
            CP_COMMIT();
        }
        uint32_t base = sb + (ch % 3) * STAGE;
        #pragma unroll
        for (int ks = 0; ks < 4; ks++) {          // 4 x k32
            uint32_t cb = (uint32_t)ks * 32 + lcol;
            uint32_t ahi[4], alo[4];
            {
                int row = m_off + lrow;
                uint32_t sw = cb ^ (((uint32_t)row & 7) << 4);
                uint32_t ad = base + (uint32_t)row * 128 + sw;
                LDMATRIX_X4(ahi[0], ahi[1], ahi[2], ahi[3], ad);
                LDMATRIX_X4(alo[0], alo[1], alo[2], alo[3], ad + 8192);
            }
            uint32_t bhi[4][2], blo[4][2];
            #pragma unroll
            for (int nt = 0; nt < 2; nt++) {
                int row = n_off + nt * 16 + lrow;
                uint32_t bd = base + 16384 + (uint32_t)row * 128 + (cb ^ (((uint32_t)row & 7) << 4));
                uint32_t r0, r1, r2, r3;
                LDMATRIX_X4(r0, r1, r2, r3, bd);
                bhi[nt * 2][0] = r0; bhi[nt * 2][1] = r2;
                bhi[nt * 2 + 1][0] = r1; bhi[nt * 2 + 1][1] = r3;
                LDMATRIX_X4(r0, r1, r2, r3, bd + 16384);
                blo[nt * 2][0] = r0; blo[nt * 2][1] = r2;
                blo[nt * 2 + 1][0] = r1; blo[nt * 2 + 1][1] = r3;
            }
            #pragma unroll
            for (int n = 0; n < 4; n++) {
                MMA_S8(acc1[n], ahi, bhi[n]);
                MMA_S8(acc2[n], ahi, blo[n]);
                MMA_S8(acc2[n], alo, bhi[n]);
            }
        }
    }

    int gid = lane >> 2, tig = lane & 3;
    int r0 = m0 + m_off + gid;
    float sa0 = __ldg(&g_sa[r0]), sa1 = __ldg(&g_sa[r0 + 8]);
    #pragma unroll
    for (int n = 0; n < 4; n++) {
        int col = n0 + n_off + n * 8 + tig * 2;
        float sb0 = __ldg(&g_sb[col]), sb1 = __ldg(&g_sb[col + 1]);
        float b0 = 0.f, b1 = 0.f;
        if (col < 3072) { b0 = __ldg(&bias[col]); b1 = __ldg(&bias[col + 1]); }
        float2 v0, v1;
        v0.x = fmaf(16384.f, (float)acc1[n][0], 128.f * (float)acc2[n][0]) * sa0 * sb0 + b0;
        v0.y = fmaf(16384.f, (float)acc1[n][1], 128.f * (float)acc2[n][1]) * sa0 * sb1 + b1;
        v1.x = fmaf(16384.f, (float)acc1[n][2], 128.f * (float)acc2[n][2]) * sa1 * sb0 + b0;
        v1.y = fmaf(16384.f, (float)acc1[n][3], 128.f * (float)acc2[n][3]) * sa1 * sb1 + b1;
        *(float2*)(g_RAW + (size_t)r0 * NRAW + col) = v0;
        *(float2*)(g_RAW + (size_t)(r0 + 8) * NRAW + col) = v1;
    }
}

// ---------------------------------------------------------------------------
// Single-pass scan with decoupled lookback.
// ---------------------------------------------------------------------------
__device__ __forceinline__ float softplus_f(float x) {
    return fmaxf(x, 0.f) + log1pf(expf(-fabsf(x)));
}
__device__ __forceinline__ float tanh_fast(float x) {
    const float L2E2 = 2.8853900817779268f;
    float ax = fabsf(x);
    float e = exp2f(ax * L2E2);
    float r = 1.0f - 2.0f / (e + 1.0f);
    return copysignf(r, x);
}
__device__ __forceinline__ void xform_ab(float dr, float brw, float alpha, float db,
                                         float gamma, float gg, float& a, float& bu,
                                         float crw, float& cv) {
    const float L2E = 1.4426950408889634f;
    float s  = dr + db;
    float t1 = exp2f(s * L2E);
    float Lg = log2f(1.0f + t1);
    a = fminf(exp2f(-alpha * Lg), 1.0f - 1e-4f);
    float bv = tanh_fast(brw);
    cv = tanh_fast(crw);
    float p  = a * a + cv * cv;
    float r2 = bv * bv;
    float q  = a * bv;
    float d1 = p - r2;
    float disc = fmaf(d1, d1, 4.0f * q * q) + 1e-12f;
    float sq   = disc * rsqrtf(disc);
    float lam  = 0.5f * (p + r2 + sq) + 1e-12f;
    float inv  = rsqrtf(fmaxf(lam, 1.0f));
    a  *= inv;
    bu  = bv * inv * gamma * gg;
    cv *= inv;
}

__global__ void __launch_bounds__(128) sp_scan(
    const float* __restrict__ alpha_log, const float* __restrict__ delta_bias,
    const float* __restrict__ log_gamma)
{
    int bid = blockIdx.x;
    int cb = bid & 7;
    int chunk = (bid >> 3) & 31;
    int b = bid >> 8;
    int tid = threadIdx.x;
    int i = cb * 128 + tid;
    size_t base = ((size_t)(b * TT + chunk * LCHUNK)) * NRAW + i;

    float alpha = softplus_f(alpha_log[i]);
    float db    = delta_bias[i];
    float gamma = expf(log_gamma[0]);

    float A = 1.f, Bc = 0.f;
    for (int t = 0; t < LCHUNK; t++) {
        size_t o = base + (size_t)t * NRAW;
        float a, bu, cv;
        xform_ab(g_RAW[o], g_RAW[o + 1024], alpha, db, gamma, g_RAW[o + 3072],
                 a, bu, g_RAW[o + 2048], cv);
        Bc = fmaf(a, Bc, bu);
        A *= a;
    }
    int ai = (b * NCHUNK + chunk) * NN + i;
    g_AggA[ai] = A;
    g_AggB[ai] = Bc;
    __threadfence();
    __syncthreads();
    if (tid == 0) atomicExch(&g_flag[bid], 1);

    float Aa = 1.f, Ba = 0.f;
    for (int p = chunk - 1; p >= 0; p--) {
        int pbid = b * 256 + p * 8 + cb;
        if (tid == 0) {
            while (atomicAdd(&g_flag[pbid], 0) == 0) { }
        }
        __syncthreads();
        int pai = (b * NCHUNK + p) * NN + i;
        float Ap = __ldcg(&g_AggA[pai]);
        float Bp = __ldcg(&g_AggB[pai]);
        Ba = fmaf(Aa, Bp, Ba);
        Aa = Aa * Ap;
    }
    float z = Ba;

    int bt0 = b * TT + chunk * LCHUNK;
    for (int t = 0; t < LCHUNK; t++) {
        size_t o = base + (size_t)t * NRAW;
        float a, bu, cv;
        xform_ab(g_RAW[o], g_RAW[o + 1024], alpha, db, gamma, g_RAW[o + 3072],
                 a, bu, g_RAW[o + 2048], cv);
        g_Yhi[(size_t)(bt0 + t) * NN + i] = __float2half_rn(cv * z);
        z = fmaf(a, z, bu);
    }
}

// ---------------------------------------------------------------------------
// Launch: main path on default stream; sigma chain forked onto side stream.
// ---------------------------------------------------------------------------
extern "C" void kernel_launch(void* const* d_in, const int* in_sizes, int n_in,
                              void* d_out, int out_size)
{
    (void)in_sizes; (void)n_in; (void)out_size;
    const float* u          = (const float*)d_in[0];
    const float* W_in       = (const float*)d_in[1];
    const float* W_out      = (const float*)d_in[2];
    const float* Wp         = (const float*)d_in[3];
    const float* bp         = (const float*)d_in[4];
    const float* alpha_log  = (const float*)d_in[5];
    const float* delta_bias = (const float*)d_in[6];
    const float* log_gamma  = (const float*)d_in[7];
    float* out = (float*)d_out;

    static cudaStream_t s_side = nullptr;
    static cudaEvent_t ev_fork = nullptr, ev_join = nullptr;
    if (s_side == nullptr) {
        cudaStreamCreateWithFlags(&s_side, cudaStreamNonBlocking);
        cudaEventCreateWithFlags(&ev_fork, cudaEventDisableTiming);
        cudaEventCreateWithFlags(&ev_join, cudaEventDisableTiming);
        cudaFuncSetAttribute((const void*)gemm1_s8,        cudaFuncAttributeMaxDynamicSharedMemorySize, SMS8);
        cudaFuncSetAttribute((const void*)mma_gemm<1, 128>, cudaFuncAttributeMaxDynamicSharedMemorySize, SM128);
        cudaFuncSetAttribute((const void*)mma_gemm<2, 64>,  cudaFuncAttributeMaxDynamicSharedMemorySize, SM64);
    }

    // ---- main stream: splits / quantization (+flag clear) ----
    split_all<<<23556, 256>>>(u, Wp, W_in, W_out);
    cudaEventRecord(ev_fork, 0);

    // ---- side stream: spectral norms ----
    cudaStreamWaitEvent(s_side, ev_fork, 0);
    init_spec<<<1, 1024, 0, s_side>>>();
    mma_gemm<2, 64><<<dim3(8, 16, 2), 512, SM64, s_side>>>(nullptr, 0);   // G0 (2-term)
    for (int k = 1; k <= NSQ; k++) {
        split_scaled<<<dim3(1024, 2), 256, 0, s_side>>>(k - 1);
        mma_gemm<2, 64><<<dim3(8, 16, 2), 512, SM64, s_side>>>(nullptr, k);  // 1-term
    }
    for (int r = 0; r < NMV; r++) {
        mv_kernel<<<dim3(64, 2), 256, 0, s_side>>>();
        vnorm_kernel<<<2, 1024, 0, s_side>>>();
    }
    rq_kernel<<<dim3(64, 2), 256, 0, s_side>>>();
    fin_sigma<<<1, 32, 0, s_side>>>();
    cudaEventRecord(ev_join, s_side);

    // ---- main stream: GEMM1 (int8) -> scan -> (join sigma) -> GEMM2 ----
    gemm1_s8<<<dim3(NRAW / GBN, BT / 64), 512, SMS8>>>(bp);
    sp_scan<<<BB * NCHUNK * 8, 128>>>(alpha_log, delta_bias, log_gamma);
    cudaStreamWaitEvent(0, ev_join, 0);
    mma_gemm<1, 128><<<dim3(NN / GBN, BT / 128), 512, SM128>>>(out, 0);
}

// round 16
// speedup vs baseline: 2.5184x; 2.5184x over previous
#include <cuda_runtime.h>
#include <cuda_fp16.h>
#include <math.h>
#include <stdint.h>

// Problem constants
#define BB   4
#define TT   4096
#define NN   1024
#define BT   16384
#define NRAW 4096
#define NCHUNK 32
#define LCHUNK 128

// GEMM tiling (HMMA mma.sync; tcgen05 unavailable: harness targets sm_103 w/o 'a')
#define GBN 128
#define GBK 64
#define KDIM 1024
#define KCH  16

#define NSQ 7
#define NMV 5

#define SM128 147456                     // 3 * (16384 + 32768)
#define SM64  122880                     // 3 * ( 8192 + 32768)

// ---------------------------------------------------------------------------
// Device scratch
// ---------------------------------------------------------------------------
__device__ __align__(128) __half g_RAWh[(size_t)BT * NRAW];           // fp16 raw [delta|b|c|g]
__device__ __align__(128) __half g_Ahi[(size_t)BT * KDIM];            // u (hi only)
__device__ __align__(128) __half g_Bhi[(size_t)NRAW * KDIM];          // [Wp(3072) ; W_in(1024)]
__device__ __align__(128) __half g_Blo[(size_t)NRAW * KDIM];
__device__ __align__(128) __half g_Whi[(size_t)NN * KDIM];            // W_out
__device__ __align__(128) __half g_Wlo[(size_t)NN * KDIM];
__device__ __align__(128) __half g_Yhi[(size_t)BT * NN];              // y_hat (hi only)
__device__ float g_AggA[BB * NCHUNK * NN];
__device__ float g_AggB[BB * NCHUNK * NN];
__device__ int   g_flag[BB * NCHUNK * 8];

// spectral-norm machinery (batched over both weights, index g in {0,1})
__device__ __align__(128) __half g_Shi[2 * 1024 * 1024];
__device__ __align__(128) __half g_Slo[2 * 1024 * 1024];
__device__ __align__(128) float g_Gk[2 * 1024 * 1024];
__device__ __align__(128) float g_G0[2 * 1024 * 1024];
__device__ float g_pv[2 * 1024];
__device__ float g_pw[2 * 1024];
__device__ float g_trace[32];
__device__ float g_acc[2];
__device__ float g_sigma[2];

// ---------------------------------------------------------------------------
// PTX helpers
// ---------------------------------------------------------------------------
__device__ __forceinline__ uint32_t smem_u32(const void* p) {
    uint32_t a;
    asm("{ .reg .u64 t; cvta.to.shared.u64 t, %1; cvt.u32.u64 %0, t; }" : "=r"(a) : "l"(p));
    return a;
}

#define CP_ASYNC16(dst, src) \
    asm volatile("cp.async.cg.shared.global [%0], [%1], 16;" :: "r"(dst), "l"(src))
#define CP_COMMIT() asm volatile("cp.async.commit_group;" ::: "memory")
#define CP_WAIT1()  asm volatile("cp.async.wait_group 1;" ::: "memory")
#define CP_WAIT0()  asm volatile("cp.async.wait_group 0;" ::: "memory")

#define LDMATRIX_X4(r0, r1, r2, r3, addr) \
    asm volatile("ldmatrix.sync.aligned.m8n8.x4.shared.b16 {%0,%1,%2,%3}, [%4];" \
                 : "=r"(r0), "=r"(r1), "=r"(r2), "=r"(r3) : "r"(addr))

#define MMA_FP16(d, a, b) \
    asm volatile("mma.sync.aligned.m16n8k16.row.col.f32.f16.f16.f32 " \
        "{%0,%1,%2,%3}, {%4,%5,%6,%7}, {%8,%9}, {%0,%1,%2,%3};" \
        : "+f"((d)[0]), "+f"((d)[1]), "+f"((d)[2]), "+f"((d)[3]) \
        : "r"((a)[0]), "r"((a)[1]), "r"((a)[2]), "r"((a)[3]), "r"((b)[0]), "r"((b)[1]))

// ---------------------------------------------------------------------------
// fp16 hi/lo split helpers
// ---------------------------------------------------------------------------
__device__ __forceinline__ void split4h(const float4 v, uint2& H, uint2& L) {
    union { __half b[4]; uint2 u; } h, l;
    float x[4] = {v.x, v.y, v.z, v.w};
    #pragma unroll
    for (int j = 0; j < 4; j++) {
        __half hb = __float2half_rn(x[j]);
        h.b[j] = hb;
        l.b[j] = __float2half_rn(x[j] - __half2float(hb));
    }
    H = h.u; L = l.u;
}
__device__ __forceinline__ uint2 hi4h(const float4 v) {
    union { __half b[4]; uint2 u; } h;
    h.b[0] = __float2half_rn(v.x); h.b[1] = __float2half_rn(v.y);
    h.b[2] = __float2half_rn(v.z); h.b[3] = __float2half_rn(v.w);
    return h.u;
}

// All input splits in ONE launch (block-range dispatch) + scan-flag clear.
__global__ void __launch_bounds__(256) split_all(
    const float* __restrict__ u, const float* __restrict__ Wp,
    const float* __restrict__ Win, const float* __restrict__ Wout)
{
    int blk = blockIdx.x, tid = threadIdx.x;
    if (blk < 16384) {
        int i = blk * 256 + tid;
        ((uint2*)g_Ahi)[i] = hi4h(((const float4*)u)[i]);
    } else if (blk < 19456) {
        int i = (blk - 16384) * 256 + tid;
        uint2 H, L; split4h(((const float4*)Wp)[i], H, L);
        ((uint2*)g_Bhi)[i] = H; ((uint2*)g_Blo)[i] = L;
    } else if (blk < 20480) {
        int i = (blk - 19456) * 256 + tid;
        uint2 H, L; split4h(((const float4*)Win)[i], H, L);
        ((uint2*)g_Bhi)[786432 + i] = H; ((uint2*)g_Blo)[786432 + i] = L;
    } else if (blk < 21504) {
        int i = (blk - 20480) * 256 + tid;
        uint2 H, L; split4h(((const float4*)Wout)[i], H, L);
        ((uint2*)g_Whi)[i] = H; ((uint2*)g_Wlo)[i] = L;
    } else if (blk < 22528) {
        int i = (blk - 21504) * 256 + tid;
        uint2 H, L; split4h(((const float4*)Win)[i], H, L);
        ((uint2*)g_Shi)[i] = H; ((uint2*)g_Slo)[i] = L;
    } else if (blk < 23552) {
        int i = (blk - 22528) * 256 + tid;
        uint2 H, L; split4h(((const float4*)Wout)[i], H, L);
        ((uint2*)g_Shi)[262144 + i] = H; ((uint2*)g_Slo)[262144 + i] = L;
    } else {
        int i = (blk - 23552) * 256 + tid;       // 4 blocks: clear 1024 lookback flags
        g_flag[i] = 0;
    }
}

// g_Gk[g] * (1024/trace[g][step]) -> g_Shi[g]  (hi only; squarings k>=1 are 1-term)
__global__ void __launch_bounds__(256) split_scaled(int step) {
    int g = blockIdx.y;
    int i = blockIdx.x * 256 + threadIdx.x;
    float s = 1024.0f / g_trace[g * 16 + step];
    float4 v = ((const float4*)(g_Gk + (size_t)g * 1048576))[i];
    v.x *= s; v.y *= s; v.z *= s; v.w *= s;
    ((uint2*)(g_Shi + (size_t)g * 1048576))[i] = hi4h(v);
}

__global__ void __launch_bounds__(1024) init_spec() {
    int t = threadIdx.x;
    float v = 0.5f + __sinf((float)t * 0.7311f);
    g_pv[t] = v;
    g_pv[1024 + t] = v;
    if (t < 32) g_trace[t] = 0.f;
    if (t < 2) g_acc[t] = 0.f;
}

// ---------------------------------------------------------------------------
// Small matvec helpers (batched over g)
// ---------------------------------------------------------------------------
__global__ void __launch_bounds__(256) mv_kernel() {
    int g = blockIdx.y;
    const float* G = g_Gk + (size_t)g * 1048576;
    const float4* V4 = (const float4*)(g_pv + g * 1024);
    int w = threadIdx.x >> 5, lane = threadIdx.x & 31;
    #pragma unroll
    for (int rr = 0; rr < 2; rr++) {
        int r = blockIdx.x * 16 + w * 2 + rr;
        const float4* Gr = (const float4*)(G + (size_t)r * 1024);
        float s = 0.f;
        #pragma unroll 4
        for (int j = lane; j < 256; j += 32) {
            float4 a = Gr[j], x = V4[j];
            s += a.x * x.x + a.y * x.y + a.z * x.z + a.w * x.w;
        }
        #pragma unroll
        for (int o = 16; o > 0; o >>= 1) s += __shfl_xor_sync(0xffffffffu, s, o);
        if (lane == 0) g_pw[g * 1024 + r] = s;
    }
}

// (restored to the validated R13 reduction)
__global__ void __launch_bounds__(1024) vnorm_kernel() {
    __shared__ float sp[32];
    int g = blockIdx.x;
    int t = threadIdx.x, lane = t & 31, w = t >> 5;
    float v = g_pw[g * 1024 + t];
    float p = v * v;
    #pragma unroll
    for (int o = 16; o > 0; o >>= 1) p += __shfl_xor_sync(0xffffffffu, p, o);
    if (lane == 0) sp[w] = p;
    __syncthreads();
    if (w == 0) {
        float q = sp[lane];
        #pragma unroll
        for (int o = 16; o > 0; o >>= 1) q += __shfl_xor_sync(0xffffffffu, q, o);
        if (lane == 0) sp[0] = rsqrtf(q);
    }
    __syncthreads();
    g_pv[g * 1024 + t] = v * sp[0];
}

// Rayleigh quotient v^T G0 v  (v unit) -> g_acc[g]
__global__ void __launch_bounds__(256) rq_kernel() {
    int g = blockIdx.y;
    const float* G0 = g_G0 + (size_t)g * 1048576;
    const float4* V4 = (const float4*)(g_pv + g * 1024);
    int w = threadIdx.x >> 5, lane = threadIdx.x & 31;
    float part = 0.f;
    #pragma unroll
    for (int rr = 0; rr < 2; rr++) {
        int r = blockIdx.x * 16 + w * 2 + rr;
        const float4* Gr = (const float4*)(G0 + (size_t)r * 1024);
        float s = 0.f;
        #pragma unroll 4
        for (int j = lane; j < 256; j += 32) {
            float4 a = Gr[j], x = V4[j];
            s += a.x * x.x + a.y * x.y + a.z * x.z + a.w * x.w;
        }
        #pragma unroll
        for (int o = 16; o > 0; o >>= 1) s += __shfl_xor_sync(0xffffffffu, s, o);
        if (lane == 0) part += s * g_pv[g * 1024 + r];
    }
    if (lane == 0) atomicAdd(&g_acc[g], part);
}

__global__ void fin_sigma() {
    if (threadIdx.x < 2)
        g_sigma[threadIdx.x] = fmaxf(1.0f, sqrtf(fmaxf(g_acc[threadIdx.x], 0.f)));
}

// ---------------------------------------------------------------------------
// HMMA GEMM (NT), fp16 2-term split: C = Ahi*Bhi (+ Ahi*Blo when two-term)
// TBM x 128 x 64 tiles, 16 warps (4m x 4n), warp tile (TBM/4) x 32, 512 thr,
// 3-stage cp.async pipeline.
// MODE 0: A=g_Ahi,  B=g_Bhi/lo (2-term), C=g_RAWh fp16 (ldc 4096), +bias col<3072
// MODE 1: A=g_Yhi,  B=g_Whi/lo (2-term), C=out fp32 (ldc 1024), * 1/(s0*s1)
// MODE 2: A=B=g_Shi[z] (+Slo only when step==0), C=g_Gk[z] (+g_G0 when step==0)
// ---------------------------------------------------------------------------
template <int TBM>
__device__ __forceinline__ void load_tiles(
    uint32_t base,
    const __half* __restrict__ Ah,
    const __half* __restrict__ Bh, const __half* __restrict__ Bl,
    int tid, bool two)
{
    constexpr uint32_t AB = TBM * 128;
    uint32_t sA = base, sBhi = base + AB, sBlo = base + AB + 16384;
    #pragma unroll
    for (int it = 0; it < TBM / 64; it++) {
        int idx = tid + it * 512;
        int r = idx >> 3, c8 = idx & 7;
        uint32_t sw = (uint32_t)r * 128 + (((uint32_t)c8 * 16) ^ (((uint32_t)r & 7) << 4));
        CP_ASYNC16(sA + sw, (const char*)(Ah + (size_t)r * KDIM) + c8 * 16);
    }
    #pragma unroll
    for (int it = 0; it < 2; it++) {
        int idx = tid + it * 512;
        int r = idx >> 3, c8 = idx & 7;
        uint32_t sw = (uint32_t)r * 128 + (((uint32_t)c8 * 16) ^ (((uint32_t)r & 7) << 4));
        CP_ASYNC16(sBhi + sw, (const char*)(Bh + (size_t)r * KDIM) + c8 * 16);
        if (two) CP_ASYNC16(sBlo + sw, (const char*)(Bl + (size_t)r * KDIM) + c8 * 16);
    }
}

template <int MODE, int TBM>
__global__ void __launch_bounds__(512, 1) mma_gemm(
    const float* __restrict__ bias, float* __restrict__ Cout, int step)
{
    constexpr int MT = TBM / 64;
    constexpr uint32_t AB = TBM * 128;
    constexpr uint32_t STAGE = AB + 32768;
    extern __shared__ char smem[];
    uint32_t sb = smem_u32(smem);
    int tid = threadIdx.x, wid = tid >> 5, lane = tid & 31;
    int m0 = blockIdx.y * TBM;
    int n0 = blockIdx.x * GBN;
    int wm = wid >> 2, wn = wid & 3;
    int m_off = wm * (TBM / 4), n_off = wn * 32;

    const bool two = (MODE != 2) || (step == 0);
    size_t goff = (MODE == 2) ? (size_t)blockIdx.z * 1048576 : 0;
    const __half* Ah = (MODE == 0 ? g_Ahi : MODE == 1 ? g_Yhi : g_Shi) + goff + (size_t)m0 * KDIM;
    const __half* Bh = (MODE == 0 ? g_Bhi : MODE == 1 ? g_Whi : g_Shi) + goff + (size_t)n0 * KDIM;
    const __half* Bl = (MODE == 0 ? g_Blo : MODE == 1 ? g_Wlo : g_Slo) + goff + (size_t)n0 * KDIM;
    float* C = (MODE == 1) ? Cout : (g_Gk + goff);
    const int ldc = (MODE == 0) ? NRAW : NN;

    float acc[MT][4][4];
    #pragma unroll
    for (int mt = 0; mt < MT; mt++)
        #pragma unroll
        for (int n = 0; n < 4; n++)
            #pragma unroll
            for (int j = 0; j < 4; j++) acc[mt][n][j] = 0.f;

    int lrow = lane & 15;
    uint32_t lcol = ((uint32_t)(lane >> 4)) << 4;

    load_tiles<TBM>(sb,         Ah,      Bh,      Bl,      tid, two); CP_COMMIT();
    load_tiles<TBM>(sb + STAGE, Ah + 64, Bh + 64, Bl + 64, tid, two); CP_COMMIT();

    for (int ch = 0; ch < KCH; ch++) {
        if (ch == KCH - 1) { CP_WAIT0(); } else { CP_WAIT1(); }
        __syncthreads();
        if (ch + 2 < KCH) {
            int k0 = (ch + 2) * GBK;
            load_tiles<TBM>(sb + ((ch + 2) % 3) * STAGE, Ah + k0, Bh + k0, Bl + k0, tid, two);
            CP_COMMIT();
        }
        uint32_t base = sb + (ch % 3) * STAGE;
        #pragma unroll
        for (int ks = 0; ks < 4; ks++) {
            uint32_t cb = (uint32_t)ks * 32 + lcol;
            uint32_t ahi[MT][4];
            #pragma unroll
            for (int mt = 0; mt < MT; mt++) {
                int row = m_off + mt * 16 + lrow;
                uint32_t ad = base + (uint32_t)row * 128 + (cb ^ (((uint32_t)row & 7) << 4));
                LDMATRIX_X4(ahi[mt][0], ahi[mt][1], ahi[mt][2], ahi[mt][3], ad);
            }
            uint32_t bhi[4][2], blo[4][2];
            #pragma unroll
            for (int nt = 0; nt < 2; nt++) {
                int row = n_off + nt * 16 + lrow;
                uint32_t bd = base + AB + (uint32_t)row * 128 + (cb ^ (((uint32_t)row & 7) << 4));
                uint32_t r0, r1, r2, r3;
                LDMATRIX_X4(r0, r1, r2, r3, bd);
                bhi[nt * 2][0] = r0; bhi[nt * 2][1] = r2;
                bhi[nt * 2 + 1][0] = r1; bhi[nt * 2 + 1][1] = r3;
                if (two) {
                    LDMATRIX_X4(r0, r1, r2, r3, bd + 16384);
                    blo[nt * 2][0] = r0; blo[nt * 2][1] = r2;
                    blo[nt * 2 + 1][0] = r1; blo[nt * 2 + 1][1] = r3;
                }
            }
            #pragma unroll
            for (int mt = 0; mt < MT; mt++)
                #pragma unroll
                for (int n = 0; n < 4; n++) {
                    MMA_FP16(acc[mt][n], ahi[mt], bhi[n]);
                    if (two) MMA_FP16(acc[mt][n], ahi[mt], blo[n]);
                }
        }
    }

    float scale = 1.0f;
    if (MODE == 1) scale = 1.0f / (g_sigma[0] * g_sigma[1]);
    int gid = lane >> 2, tig = lane & 3;
    float tp = 0.f;
    bool diag = (MODE == 2) && (m0 < n0 + GBN) && (n0 < m0 + TBM);

    #pragma unroll
    for (int mt = 0; mt < MT; mt++) {
        #pragma unroll
        for (int n = 0; n < 4; n++) {
            int col = n0 + n_off + n * 8 + tig * 2;
            int r0 = m0 + m_off + mt * 16 + gid;
            float2 v0 = make_float2(acc[mt][n][0], acc[mt][n][1]);
            float2 v1 = make_float2(acc[mt][n][2], acc[mt][n][3]);
            if (MODE == 0) {
                if (col < 3072) {
                    float b0 = __ldg(&bias[col]), b1 = __ldg(&bias[col + 1]);
                    v0.x += b0; v0.y += b1; v1.x += b0; v1.y += b1;
                }
                *(__half2*)(g_RAWh + (size_t)r0 * NRAW + col) = __floats2half2_rn(v0.x, v0.y);
                *(__half2*)(g_RAWh + (size_t)(r0 + 8) * NRAW + col) = __floats2half2_rn(v1.x, v1.y);
                continue;
            } else if (MODE == 1) {
                v0.x *= scale; v0.y *= scale; v1.x *= scale; v1.y *= scale;
            } else if (diag) {
                if (r0 == col)         tp += v0.x;
                if (r0 == col + 1)     tp += v0.y;
                if (r0 + 8 == col)     tp += v1.x;
                if (r0 + 8 == col + 1) tp += v1.y;
            }
            *(float2*)(C + (size_t)r0 * ldc + col) = v0;
            *(float2*)(C + (size_t)(r0 + 8) * ldc + col) = v1;
            if (MODE == 2 && step == 0) {
                float* C0 = g_G0 + goff;
                *(float2*)(C0 + (size_t)r0 * ldc + col) = v0;
                *(float2*)(C0 + (size_t)(r0 + 8) * ldc + col) = v1;
            }
        }
    }
    if (MODE == 2 && diag && tp != 0.f)
        atomicAdd(&g_trace[blockIdx.z * 16 + step], tp);
}

// ---------------------------------------------------------------------------
// Single-pass scan with decoupled lookback (fp16 raw inputs).
// ---------------------------------------------------------------------------
__device__ __forceinline__ float softplus_f(float x) {
    return fmaxf(x, 0.f) + log1pf(expf(-fabsf(x)));
}
__device__ __forceinline__ float tanh_fast(float x) {
    const float L2E2 = 2.8853900817779268f;
    float ax = fabsf(x);
    float e = exp2f(ax * L2E2);
    float r = 1.0f - 2.0f / (e + 1.0f);
    return copysignf(r, x);
}
__device__ __forceinline__ void xform_ab(float dr, float brw, float alpha, float db,
                                         float gamma, float gg, float& a, float& bu,
                                         float crw, float& cv) {
    const float L2E = 1.4426950408889634f;
    float s  = dr + db;
    float t1 = exp2f(s * L2E);
    float Lg = log2f(1.0f + t1);
    a = fminf(exp2f(-alpha * Lg), 1.0f - 1e-4f);
    float bv = tanh_fast(brw);
    cv = tanh_fast(crw);
    float p  = a * a + cv * cv;
    float r2 = bv * bv;
    float q  = a * bv;
    float d1 = p - r2;
    float disc = fmaf(d1, d1, 4.0f * q * q) + 1e-12f;
    float sq   = disc * rsqrtf(disc);
    float lam  = 0.5f * (p + r2 + sq) + 1e-12f;
    float inv  = rsqrtf(fmaxf(lam, 1.0f));
    a  *= inv;
    bu  = bv * inv * gamma * gg;
    cv *= inv;
}

__global__ void __launch_bounds__(128) sp_scan(
    const float* __restrict__ alpha_log, const float* __restrict__ delta_bias,
    const float* __restrict__ log_gamma)
{
    int bid = blockIdx.x;
    int cb = bid & 7;
    int chunk = (bid >> 3) & 31;
    int b = bid >> 8;
    int tid = threadIdx.x;
    int i = cb * 128 + tid;
    size_t base = ((size_t)(b * TT + chunk * LCHUNK)) * NRAW + i;

    float alpha = softplus_f(alpha_log[i]);
    float db    = delta_bias[i];
    float gamma = expf(log_gamma[0]);

    // sweep1: aggregates
    float A = 1.f, Bc = 0.f;
    for (int t = 0; t < LCHUNK; t++) {
        size_t o = base + (size_t)t * NRAW;
        float a, bu, cv;
        xform_ab(__half2float(g_RAWh[o]), __half2float(g_RAWh[o + 1024]),
                 alpha, db, gamma, __half2float(g_RAWh[o + 3072]),
                 a, bu, __half2float(g_RAWh[o + 2048]), cv);
        Bc = fmaf(a, Bc, bu);
        A *= a;
    }
    int ai = (b * NCHUNK + chunk) * NN + i;
    g_AggA[ai] = A;
    g_AggB[ai] = Bc;
    __threadfence();
    __syncthreads();
    if (tid == 0) atomicExch(&g_flag[bid], 1);

    // lookback
    float Aa = 1.f, Ba = 0.f;
    for (int p = chunk - 1; p >= 0; p--) {
        int pbid = b * 256 + p * 8 + cb;
        if (tid == 0) {
            while (atomicAdd(&g_flag[pbid], 0) == 0) { }
        }
        __syncthreads();
        int pai = (b * NCHUNK + p) * NN + i;
        float Ap = __ldcg(&g_AggA[pai]);
        float Bp = __ldcg(&g_AggB[pai]);
        Ba = fmaf(Aa, Bp, Ba);
        Aa = Aa * Ap;
    }
    float z = Ba;

    // sweep2: emit y_hat = c_t * z_t
    int bt0 = b * TT + chunk * LCHUNK;
    for (int t = 0; t < LCHUNK; t++) {
        size_t o = base + (size_t)t * NRAW;
        float a, bu, cv;
        xform_ab(__half2float(g_RAWh[o]), __half2float(g_RAWh[o + 1024]),
                 alpha, db, gamma, __half2float(g_RAWh[o + 3072]),
                 a, bu, __half2float(g_RAWh[o + 2048]), cv);
        g_Yhi[(size_t)(bt0 + t) * NN + i] = __float2half_rn(cv * z);
        z = fmaf(a, z, bu);
    }
}

// ---------------------------------------------------------------------------
// Launch: main path on default stream; sigma chain forked onto side stream.
// ---------------------------------------------------------------------------
extern "C" void kernel_launch(void* const* d_in, const int* in_sizes, int n_in,
                              void* d_out, int out_size)
{
    (void)in_sizes; (void)n_in; (void)out_size;
    const float* u          = (const float*)d_in[0];
    const float* W_in       = (const float*)d_in[1];
    const float* W_out      = (const float*)d_in[2];
    const float* Wp         = (const float*)d_in[3];
    const float* bp         = (const float*)d_in[4];
    const float* alpha_log  = (const float*)d_in[5];
    const float* delta_bias = (const float*)d_in[6];
    const float* log_gamma  = (const float*)d_in[7];
    float* out = (float*)d_out;

    static cudaStream_t s_side = nullptr;
    static cudaEvent_t ev_fork = nullptr, ev_join = nullptr;
    if (s_side == nullptr) {
        cudaStreamCreateWithFlags(&s_side, cudaStreamNonBlocking);
        cudaEventCreateWithFlags(&ev_fork, cudaEventDisableTiming);
        cudaEventCreateWithFlags(&ev_join, cudaEventDisableTiming);
        cudaFuncSetAttribute((const void*)mma_gemm<0, 128>, cudaFuncAttributeMaxDynamicSharedMemorySize, SM128);
        cudaFuncSetAttribute((const void*)mma_gemm<1, 128>, cudaFuncAttributeMaxDynamicSharedMemorySize, SM128);
        cudaFuncSetAttribute((const void*)mma_gemm<2, 64>,  cudaFuncAttributeMaxDynamicSharedMemorySize, SM64);
    }

    // ---- main stream: splits (+flag clear) ----
    split_all<<<23556, 256>>>(u, Wp, W_in, W_out);
    cudaEventRecord(ev_fork, 0);

    // ---- side stream: spectral norms ----
    cudaStreamWaitEvent(s_side, ev_fork, 0);
    init_spec<<<1, 1024, 0, s_side>>>();
    mma_gemm<2, 64><<<dim3(8, 16, 2), 512, SM64, s_side>>>(nullptr, nullptr, 0);  // G0 (2-term)
    for (int k = 1; k <= NSQ; k++) {
        split_scaled<<<dim3(1024, 2), 256, 0, s_side>>>(k - 1);
        mma_gemm<2, 64><<<dim3(8, 16, 2), 512, SM64, s_side>>>(nullptr, nullptr, k);  // 1-term
    }
    for (int r = 0; r < NMV; r++) {
        mv_kernel<<<dim3(64, 2), 256, 0, s_side>>>();
        vnorm_kernel<<<2, 1024, 0, s_side>>>();
    }
    rq_kernel<<<dim3(64, 2), 256, 0, s_side>>>();
    fin_sigma<<<1, 32, 0, s_side>>>();
    cudaEventRecord(ev_join, s_side);

    // ---- main stream: GEMM1 -> scan -> (join sigma) -> GEMM2 ----
    mma_gemm<0, 128><<<dim3(NRAW / GBN, BT / 128), 512, SM128>>>(bp, nullptr, 0);
    sp_scan<<<BB * NCHUNK * 8, 128>>>(alpha_log, delta_bias, log_gamma);
    cudaStreamWaitEvent(0, ev_join, 0);
    mma_gemm<1, 128><<<dim3(NN / GBN, BT / 128), 512, SM128>>>(nullptr, out, 0);
}